// round 6
// baseline (speedup 1.0000x reference)
#include <cuda_runtime.h>
#include <cstdint>
#include <cmath>

// SA neuron forward scan — time-parallel chunked scan, float4-vectorized,
// batch-halved for L2 reuse of the input between P1 and P3.
//
// Input : input_current [B=16, T, F=1024] float32 (T=2000 here)
// Output: d_out = concat(imem_trace [B, T+1, F] f32, spikes [B, T+1, F] f32)
//
// While no neuron fires, i_ahp = i_ref = 0 identically and the membrane is a
// linear AR(1). Per batch-half (8 batches = 65.5 MB input, fits L2):
//   P1: per (neuron4, chunk) linear partial from z=0   [reads x, stays in L2]
//   P2: per neuron carry combine zc' = a^L zc + s_j    [tiny]
//   P3: per (neuron4, chunk) exact nonlinear replay    [re-reads x from L2,
//       writes outputs via evict-first stores]
//   FB: serial exact recompute for any neuron that fired (correct for any
//       input; no-op here)

namespace sa {
constexpr double d_TAU_M   = 1e-13 * 0.026 / (0.7 * 2.5e-11);
constexpr double d_DT_S    = (d_TAU_M * 1000.0 / 20.0) * 0.001;
constexpr double d_TAU_AHP = 2.5e-13 * 0.026 / (0.7 * 2e-11);
constexpr double d_TAU_REF = 2e-13 * 0.026 / (0.7 * 1.6e-9);

__device__ __host__ __forceinline__ float f_CUR_SCALE() { return 1e-12f; }
__device__ __host__ __forceinline__ float f_ONE_MINUS_A() { return 0.2f; }
__device__ __host__ __forceinline__ float f_INV_TAU_M() { return (float)(1.0 / d_TAU_M); }
__device__ __host__ __forceinline__ float f_DT_S() { return (float)d_DT_S; }
__device__ __host__ __forceinline__ float f_K_AHP() { return (float)(d_DT_S / d_TAU_AHP); }
__device__ __host__ __forceinline__ float f_K_REF() { return (float)(d_DT_S / d_TAU_REF); }
__device__ __host__ __forceinline__ float f_Z_TH() { return 2.5e-9f; }
__device__ __host__ __forceinline__ float f_R() { return 332.0f; }
__device__ __host__ __forceinline__ float f_I_TH_AHP() { return 1.66e-11f; }
__device__ __host__ __forceinline__ float f_I_REF_ADD() { return 1.6e-9f; }
} // namespace sa

constexpr int B_C = 16;
constexpr int F_C = 1024;
constexpr int N_C = B_C * F_C;          // 16384 neurons
constexpr int L_C = 50;                 // chunk length
constexpr int K_MAX = 128;              // supports T up to 6400

// Scratch (allocation-free rule: __device__ globals)
__device__ float    g_s[K_MAX][N_C];      // chunk partials (zero-carry result)
__device__ float    g_carry[K_MAX][N_C];  // carry-in z per chunk
__device__ unsigned g_flags[N_C];         // per-neuron "fired somewhere" flag

// ---------------------------------------------------------------------------
// P1: chunk partials, linear (no-fire) dynamics from z=0. float4/thread.
// grid: (nb*F/4/128, K). Default load policy -> input stays L2-resident.
// ---------------------------------------------------------------------------
__global__ __launch_bounds__(128)
void sa_p1_partials(const float* __restrict__ in, int T, int b0)
{
    const int n4 = (b0 * F_C / 4) + blockIdx.x * blockDim.x + threadIdx.x;
    const int j  = blockIdx.y;
    const int t0 = j * L_C;
    if (t0 >= T) return;
    const int n = n4 * 4;
    const int b = n >> 10;
    const int f = n & (F_C - 1);
    const float* __restrict__ xp = in + (size_t)b * T * F_C + (size_t)t0 * F_C + f;

    const float cs  = sa::f_CUR_SCALE();
    const float oma = sa::f_ONE_MINUS_A();
    const float itm = sa::f_INV_TAU_M();
    const float dt  = sa::f_DT_S();

    float4 z = make_float4(0.f, 0.f, 0.f, 0.f);
    const int cnt = min(L_C, T - t0);

    if (cnt == L_C) {
        #pragma unroll 10
        for (int i = 0; i < L_C; i++) {
            const float4 x = __ldg((const float4*)(xp + (size_t)i * F_C));
            z.x = fmaf(dt, fmaf(-oma, z.x, x.x * cs) * itm, z.x);
            z.y = fmaf(dt, fmaf(-oma, z.y, x.y * cs) * itm, z.y);
            z.z = fmaf(dt, fmaf(-oma, z.z, x.z * cs) * itm, z.z);
            z.w = fmaf(dt, fmaf(-oma, z.w, x.w * cs) * itm, z.w);
        }
    } else {
        for (int i = 0; i < cnt; i++) {
            const float4 x = __ldg((const float4*)(xp + (size_t)i * F_C));
            z.x = fmaf(dt, fmaf(-oma, z.x, x.x * cs) * itm, z.x);
            z.y = fmaf(dt, fmaf(-oma, z.y, x.y * cs) * itm, z.y);
            z.z = fmaf(dt, fmaf(-oma, z.z, x.z * cs) * itm, z.z);
            z.w = fmaf(dt, fmaf(-oma, z.w, x.w * cs) * itm, z.w);
        }
    }
    *(float4*)&g_s[j][n] = z;
}

// ---------------------------------------------------------------------------
// P2: carry combine per neuron. Loads batched (independent), then a short
// dependent FMA chain. Also zeroes flags + imem[:,0,:] for its batch range.
// ---------------------------------------------------------------------------
__global__ __launch_bounds__(128)
void sa_p2_carry(float* __restrict__ imem, int T, int K, float aL, float a1,
                 int b0)
{
    const int n = b0 * F_C + blockIdx.x * blockDim.x + threadIdx.x;
    g_flags[n] = 0u;

    float s[K_MAX];
    #pragma unroll 8
    for (int j = 0; j < K; j++) s[j] = g_s[j][n];   // independent, batched

    float zc = 0.0f;
    for (int j = 0; j < K; j++) {
        g_carry[j][n] = zc;
        const int cnt = min(L_C, T - j * L_C);
        const float aj = (cnt == L_C) ? aL : __powf(a1, (float)cnt);
        zc = fmaf(aj, zc, s[j]);
    }

    // imem_trace[:,0,:] = 0
    const int b = n >> 10;
    const int f = n & (F_C - 1);
    imem[(size_t)b * (T + 1) * F_C + f] = 0.0f;
}

// ---------------------------------------------------------------------------
// P3: exact nonlinear replay per (neuron4, chunk) from the linear carry.
// Input re-read should hit L2 (loaded by P1 moments ago); outputs streamed.
// ---------------------------------------------------------------------------
__global__ __launch_bounds__(128)
void sa_p3_replay(const float* __restrict__ in,
                  float* __restrict__ imem,
                  float* __restrict__ spk, int T, int b0)
{
    const int n4 = (b0 * F_C / 4) + blockIdx.x * blockDim.x + threadIdx.x;
    const int j  = blockIdx.y;
    const int t0 = j * L_C;
    if (t0 >= T) return;
    const int n = n4 * 4;
    const int b = n >> 10;
    const int f = n & (F_C - 1);

    const float* __restrict__ xp = in + (size_t)b * T * F_C + (size_t)t0 * F_C + f;
    float* __restrict__ ip = imem + (size_t)b * (T + 1) * F_C + (size_t)(t0 + 1) * F_C + f;
    float* __restrict__ sp = spk  + (size_t)b * (T + 1) * F_C + (size_t)t0 * F_C + f;

    const float cs   = sa::f_CUR_SCALE();
    const float oma  = sa::f_ONE_MINUS_A();
    const float itm  = sa::f_INV_TAU_M();
    const float dt   = sa::f_DT_S();
    const float kah  = sa::f_K_AHP();
    const float kre  = sa::f_K_REF();
    const float zth  = sa::f_Z_TH();
    const float rg   = sa::f_R();
    const float aah  = sa::f_I_TH_AHP();
    const float are  = sa::f_I_REF_ADD();

    float4 z   = *(const float4*)&g_carry[j][n];
    float4 ahp = make_float4(0.f, 0.f, 0.f, 0.f);
    float4 ref = make_float4(0.f, 0.f, 0.f, 0.f);
    unsigned fired_mask = 0u;
    float4 lastf = make_float4(0.f, 0.f, 0.f, 0.f);

    const int cnt = min(L_C, T - t0);

    #define SA_STEP(ZC, AC, RC, XC, FC, BIT)                                  \
        {                                                                     \
            const float i_net = fmaf(XC, cs, -(AC) - (RC));                   \
            ZC = fmaf(dt, fmaf(-oma, ZC, i_net) * itm, ZC);                   \
            const bool fd = (ZC >= zth);                                      \
            ZC = fd ? 0.0f : ZC;                                              \
            AC = fmaf(AC, -kah, AC);                                          \
            RC = fmaf(RC, -kre, RC);                                          \
            if (fd) { AC += aah; RC += are; fired_mask |= (1u << BIT); }      \
            FC = fd ? 1.0f : 0.0f;                                            \
        }

    if (cnt == L_C) {
        #pragma unroll 10
        for (int i = 0; i < L_C; i++) {
            const float4 x = __ldcs((const float4*)(xp + (size_t)i * F_C));
            float4 ff;
            SA_STEP(z.x, ahp.x, ref.x, x.x, ff.x, 0)
            SA_STEP(z.y, ahp.y, ref.y, x.y, ff.y, 1)
            SA_STEP(z.z, ahp.z, ref.z, x.z, ff.z, 2)
            SA_STEP(z.w, ahp.w, ref.w, x.w, ff.w, 3)
            const float4 im = make_float4(z.x * rg, z.y * rg, z.z * rg, z.w * rg);
            __stcs((float4*)(ip + (size_t)i * F_C), im);
            __stcs((float4*)(sp + (size_t)i * F_C), ff);
            lastf = ff;
        }
    } else {
        for (int i = 0; i < cnt; i++) {
            const float4 x = __ldcs((const float4*)(xp + (size_t)i * F_C));
            float4 ff;
            SA_STEP(z.x, ahp.x, ref.x, x.x, ff.x, 0)
            SA_STEP(z.y, ahp.y, ref.y, x.y, ff.y, 1)
            SA_STEP(z.z, ahp.z, ref.z, x.z, ff.z, 2)
            SA_STEP(z.w, ahp.w, ref.w, x.w, ff.w, 3)
            const float4 im = make_float4(z.x * rg, z.y * rg, z.z * rg, z.w * rg);
            __stcs((float4*)(ip + (size_t)i * F_C), im);
            __stcs((float4*)(sp + (size_t)i * F_C), ff);
            lastf = ff;
        }
    }
    #undef SA_STEP

    if (t0 + cnt == T) {
        __stcs((float4*)(sp + (size_t)cnt * F_C), lastf);   // spikes[:,T,:]
    }
    if (fired_mask) {
        if (fired_mask & 1u) g_flags[n + 0] = 1u;
        if (fired_mask & 2u) g_flags[n + 1] = 1u;
        if (fired_mask & 4u) g_flags[n + 2] = 1u;
        if (fired_mask & 8u) g_flags[n + 3] = 1u;
    }
}

// ---------------------------------------------------------------------------
// FB: exact serial recompute for flagged neurons (correctness insurance).
// ---------------------------------------------------------------------------
__global__ __launch_bounds__(128)
void sa_fallback(const float* __restrict__ in,
                 float* __restrict__ imem,
                 float* __restrict__ spk, int T)
{
    const int n = blockIdx.x * blockDim.x + threadIdx.x;
    if (n >= N_C) return;
    if (g_flags[n] == 0u) return;

    const int b = n >> 10;
    const int f = n & (F_C - 1);
    const float* __restrict__ xp = in + (size_t)b * T * F_C + f;
    float* __restrict__ ip = imem + (size_t)b * (T + 1) * F_C + f;
    float* __restrict__ sp = spk  + (size_t)b * (T + 1) * F_C + f;

    const float cs  = sa::f_CUR_SCALE();
    const float oma = sa::f_ONE_MINUS_A();
    const float itm = sa::f_INV_TAU_M();
    const float dt  = sa::f_DT_S();
    const float kah = sa::f_K_AHP();
    const float kre = sa::f_K_REF();
    const float zth = sa::f_Z_TH();
    const float rg  = sa::f_R();
    const float aah = sa::f_I_TH_AHP();
    const float are = sa::f_I_REF_ADD();

    ip[0] = 0.0f;
    float z = 0.0f, ahp = 0.0f, ref = 0.0f;
    float lastf = 0.0f;
    for (int t = 0; t < T; t++) {
        const float x = xp[(size_t)t * F_C];
        const float i_net = fmaf(x, cs, -ahp - ref);
        z = fmaf(dt, fmaf(-oma, z, i_net) * itm, z);
        const bool fd = (z >= zth);
        z = fd ? 0.0f : z;
        ahp = fmaf(ahp, -kah, ahp);
        ref = fmaf(ref, -kre, ref);
        if (fd) { ahp += aah; ref += are; }
        const float ff = fd ? 1.0f : 0.0f;
        ip[(size_t)(t + 1) * F_C] = z * rg;
        sp[(size_t)t * F_C] = ff;
        lastf = ff;
    }
    sp[(size_t)T * F_C] = lastf;
}

// ---------------------------------------------------------------------------
extern "C" void kernel_launch(void* const* d_in, const int* in_sizes, int n_in,
                              void* d_out, int out_size)
{
    (void)n_in;
    const int T = in_sizes[0] / (B_C * F_C);       // 2000
    const int K = (T + L_C - 1) / L_C;             // 40
    const int half = out_size / 2;

    const float* in = (const float*)d_in[0];
    float* imem_out = (float*)d_out;
    float* spk_out  = (float*)d_out + half;

    const double a_d = 1.0 - sa::d_DT_S * 0.2 / sa::d_TAU_M;    // 0.99
    const float  aL  = (float)std::pow(a_d, (double)L_C);
    const float  a1  = (float)a_d;

    constexpr int HB = B_C / 2;                    // 8 batches per half
    dim3 blk(128);
    dim3 grid_nk4(HB * F_C / 4 / 128, K);          // (16, K) per half
    dim3 grid_n(HB * F_C / 128);                   // 64 per half
    dim3 grid_nfull(N_C / 128);                    // 128

    for (int h = 0; h < 2; h++) {
        const int b0 = h * HB;
        sa_p1_partials<<<grid_nk4, blk>>>(in, T, b0);
        sa_p2_carry  <<<grid_n,   blk>>>(imem_out, T, K, aL, a1, b0);
        sa_p3_replay <<<grid_nk4, blk>>>(in, imem_out, spk_out, T, b0);
    }
    sa_fallback<<<grid_nfull, blk>>>(in, imem_out, spk_out, T);
}

// round 7
// speedup vs baseline: 1.1147x; 1.1147x over previous
#include <cuda_runtime.h>
#include <cstdint>
#include <cmath>

// SA neuron forward scan — single-pass chunked scan with decoupled look-back.
//
// Input : input_current [B=16, T, F=1024] float32 (T=2000 here)
// Output: d_out = concat(imem_trace [B, T+1, F] f32, spikes [B, T+1, F] f32)
//
// While no neuron fires, i_ahp = i_ref = 0 and the membrane is a linear AR(1)
// (z' = a z + c x, a = 0.99). One persistent-style kernel, block = (chunk j,
// 512-neuron slice):
//   1. stage the x slab into smem (per-thread private columns)
//   2. linear partial s_j from smem; publish (aggregate flag)
//   3. decoupled look-back -> exclusive carry E_j; publish inclusive prefix
//   4. exact nonlinear replay from E_j using the smem slab; stream outputs;
//      flag any neuron that fires
// A serial exact fallback kernel repairs flagged neurons (correct for any
// input; no-op for this one). x is read from DRAM exactly once.

namespace sa {
constexpr double d_TAU_M   = 1e-13 * 0.026 / (0.7 * 2.5e-11);
constexpr double d_DT_S    = (d_TAU_M * 1000.0 / 20.0) * 0.001;
constexpr double d_TAU_AHP = 2.5e-13 * 0.026 / (0.7 * 2e-11);
constexpr double d_TAU_REF = 2e-13 * 0.026 / (0.7 * 1.6e-9);

__device__ __host__ __forceinline__ float f_CUR_SCALE() { return 1e-12f; }
__device__ __host__ __forceinline__ float f_ONE_MINUS_A() { return 0.2f; }
__device__ __host__ __forceinline__ float f_INV_TAU_M() { return (float)(1.0 / d_TAU_M); }
__device__ __host__ __forceinline__ float f_DT_S() { return (float)d_DT_S; }
__device__ __host__ __forceinline__ float f_K_AHP() { return (float)(d_DT_S / d_TAU_AHP); }
__device__ __host__ __forceinline__ float f_K_REF() { return (float)(d_DT_S / d_TAU_REF); }
__device__ __host__ __forceinline__ float f_Z_TH() { return 2.5e-9f; }
__device__ __host__ __forceinline__ float f_R() { return 332.0f; }
__device__ __host__ __forceinline__ float f_I_TH_AHP() { return 1.66e-11f; }
__device__ __host__ __forceinline__ float f_I_REF_ADD() { return 1.6e-9f; }
} // namespace sa

constexpr int B_C = 16;
constexpr int F_C = 1024;
constexpr int N_C = B_C * F_C;           // 16384 neurons
constexpr int N4_C = N_C / 4;            // 4096 float4 lanes
constexpr int THR = 128;                 // threads per block
constexpr int SLICES = N4_C / THR;       // 32 slices of 512 neurons
constexpr int L_C = 25;                  // chunk length (K = ceil(T/L))
constexpr int K_MAX = 256;               // supports T up to 6400
constexpr int SMEM_BYTES = THR * L_C * 16;  // 51200 B

// Scratch (allocation-free rule: __device__ globals; zero-initialized at load)
__device__ float    g_s[K_MAX][N_C];        // chunk aggregates
__device__ float    g_inc[K_MAX][N_C];      // inclusive prefixes
__device__ int      g_state[K_MAX * SLICES];// 0 none / 1 aggregate / 2 inclusive
__device__ unsigned g_flags[N_C];           // per-neuron fired flag (sticky)

__device__ __forceinline__ void st_release_gpu(int* p, int v) {
    asm volatile("st.release.gpu.s32 [%0], %1;" :: "l"(p), "r"(v) : "memory");
}
__device__ __forceinline__ int ld_acquire_gpu(const int* p) {
    int v;
    asm volatile("ld.acquire.gpu.s32 %0, [%1];" : "=r"(v) : "l"(p) : "memory");
    return v;
}

// ---------------------------------------------------------------------------
__global__ void sa_init(int K)
{
    const int i = blockIdx.x * blockDim.x + threadIdx.x;
    if (i < K * SLICES) g_state[i] = 0;
}

// ---------------------------------------------------------------------------
__global__ __launch_bounds__(THR)
void sa_main(const float* __restrict__ in,
             float* __restrict__ imem,
             float* __restrict__ spk,
             int T, float aL)
{
    extern __shared__ float4 sx[];           // [L_C][THR], thread-private cols
    __shared__ int s_flag;

    const int slice = blockIdx.x & (SLICES - 1);
    const int j     = blockIdx.x / SLICES;
    const int tid   = threadIdx.x;
    const int t0    = j * L_C;
    const int n4    = slice * THR + tid;
    const int n     = n4 * 4;
    const int b     = n >> 10;
    const int f     = n & (F_C - 1);
    const int cnt   = min(L_C, T - t0);

    const float cs  = sa::f_CUR_SCALE();
    const float oma = sa::f_ONE_MINUS_A();
    const float itm = sa::f_INV_TAU_M();
    const float dt  = sa::f_DT_S();

    const float4* __restrict__ xp =
        (const float4*)(in + (size_t)b * T * F_C + (size_t)t0 * F_C + f);

    // ---- 1. stage x slab into smem (independent loads -> max MLP) ----
    #pragma unroll
    for (int i = 0; i < L_C; i++) {
        if (i < cnt) sx[i * THR + tid] = __ldcs(xp + (size_t)i * (F_C / 4));
    }

    // ---- 2. linear partial from z=0 (reads own smem column) ----
    float4 s = make_float4(0.f, 0.f, 0.f, 0.f);
    #pragma unroll
    for (int i = 0; i < L_C; i++) {
        if (i >= cnt) break;
        const float4 x = sx[i * THR + tid];
        s.x = fmaf(dt, fmaf(-oma, s.x, x.x * cs) * itm, s.x);
        s.y = fmaf(dt, fmaf(-oma, s.y, x.y * cs) * itm, s.y);
        s.z = fmaf(dt, fmaf(-oma, s.z, x.z * cs) * itm, s.z);
        s.w = fmaf(dt, fmaf(-oma, s.w, x.w * cs) * itm, s.w);
    }

    // ---- 3. publish aggregate (or inclusive for j==0), look-back ----
    float4 E = make_float4(0.f, 0.f, 0.f, 0.f);   // exclusive carry
    if (j == 0) {
        *(float4*)&g_inc[0][n] = s;
        __threadfence();
        __syncthreads();
        if (tid == 0) st_release_gpu(&g_state[slice], 2);
    } else {
        *(float4*)&g_s[j][n] = s;
        __threadfence();
        __syncthreads();
        if (tid == 0) st_release_gpu(&g_state[j * SLICES + slice], 1);

        // decoupled look-back: E_j = sum_{m<j} a^{L(j-1-m)} s_m, early-exit
        // on an inclusive prefix.
        float c = 1.0f;
        for (int m = j - 1; m >= 0; m--) {
            if (tid == 0) {
                int st;
                while ((st = ld_acquire_gpu(&g_state[m * SLICES + slice])) == 0)
                    __nanosleep(20);
                s_flag = st;
            }
            __syncthreads();
            const int st = s_flag;
            if (st == 2) {
                const float4 v = __ldcg((const float4*)&g_inc[m][n]);
                E.x = fmaf(c, v.x, E.x); E.y = fmaf(c, v.y, E.y);
                E.z = fmaf(c, v.z, E.z); E.w = fmaf(c, v.w, E.w);
                __syncthreads();
                break;
            } else {
                const float4 v = __ldcg((const float4*)&g_s[m][n]);
                E.x = fmaf(c, v.x, E.x); E.y = fmaf(c, v.y, E.y);
                E.z = fmaf(c, v.z, E.z); E.w = fmaf(c, v.w, E.w);
                c *= aL;
            }
            __syncthreads();   // protect s_flag reuse
        }

        // publish inclusive prefix: inc_j = a^L * E_j + s_j
        float4 inc;
        inc.x = fmaf(aL, E.x, s.x); inc.y = fmaf(aL, E.y, s.y);
        inc.z = fmaf(aL, E.z, s.z); inc.w = fmaf(aL, E.w, s.w);
        *(float4*)&g_inc[j][n] = inc;
        __threadfence();
        __syncthreads();
        if (tid == 0) st_release_gpu(&g_state[j * SLICES + slice], 2);
    }

    // ---- 4. exact nonlinear replay from E using the smem slab ----
    float* __restrict__ ip = imem + (size_t)b * (T + 1) * F_C + (size_t)(t0 + 1) * F_C + f;
    float* __restrict__ sp = spk  + (size_t)b * (T + 1) * F_C + (size_t)t0 * F_C + f;

    const float kah = sa::f_K_AHP();
    const float kre = sa::f_K_REF();
    const float zth = sa::f_Z_TH();
    const float rg  = sa::f_R();
    const float aah = sa::f_I_TH_AHP();
    const float are = sa::f_I_REF_ADD();

    float4 z   = E;
    float4 ahp = make_float4(0.f, 0.f, 0.f, 0.f);
    float4 ref = make_float4(0.f, 0.f, 0.f, 0.f);
    unsigned fired_mask = 0u;
    float4 lastf = make_float4(0.f, 0.f, 0.f, 0.f);

    #define SA_STEP(ZC, AC, RC, XC, FC, BIT)                                  \
        {                                                                     \
            const float i_net = fmaf(XC, cs, -(AC) - (RC));                   \
            ZC = fmaf(dt, fmaf(-oma, ZC, i_net) * itm, ZC);                   \
            const bool fd = (ZC >= zth);                                      \
            ZC = fd ? 0.0f : ZC;                                              \
            AC = fmaf(AC, -kah, AC);                                          \
            RC = fmaf(RC, -kre, RC);                                          \
            if (fd) { AC += aah; RC += are; fired_mask |= (1u << BIT); }      \
            FC = fd ? 1.0f : 0.0f;                                            \
        }

    #pragma unroll
    for (int i = 0; i < L_C; i++) {
        if (i >= cnt) break;
        const float4 x = sx[i * THR + tid];
        float4 ff;
        SA_STEP(z.x, ahp.x, ref.x, x.x, ff.x, 0)
        SA_STEP(z.y, ahp.y, ref.y, x.y, ff.y, 1)
        SA_STEP(z.z, ahp.z, ref.z, x.z, ff.z, 2)
        SA_STEP(z.w, ahp.w, ref.w, x.w, ff.w, 3)
        const float4 im = make_float4(z.x * rg, z.y * rg, z.z * rg, z.w * rg);
        __stcs((float4*)(ip + (size_t)i * F_C), im);
        __stcs((float4*)(sp + (size_t)i * F_C), ff);
        lastf = ff;
    }
    #undef SA_STEP

    if (j == 0) {
        // imem_trace[:,0,:] = 0
        __stcs((float4*)(imem + (size_t)b * (T + 1) * F_C + f),
               make_float4(0.f, 0.f, 0.f, 0.f));
    }
    if (t0 + cnt == T) {
        // spikes[:,T,:] = fired_{T-1}
        __stcs((float4*)(sp + (size_t)cnt * F_C), lastf);
    }
    if (fired_mask) {   // sticky flags; fallback repairs exactly (idempotent)
        if (fired_mask & 1u) g_flags[n + 0] = 1u;
        if (fired_mask & 2u) g_flags[n + 1] = 1u;
        if (fired_mask & 4u) g_flags[n + 2] = 1u;
        if (fired_mask & 8u) g_flags[n + 3] = 1u;
    }
}

// ---------------------------------------------------------------------------
// FB: exact serial recompute for flagged neurons (correctness insurance).
// ---------------------------------------------------------------------------
__global__ __launch_bounds__(128)
void sa_fallback(const float* __restrict__ in,
                 float* __restrict__ imem,
                 float* __restrict__ spk, int T)
{
    const int n = blockIdx.x * blockDim.x + threadIdx.x;
    if (n >= N_C) return;
    if (g_flags[n] == 0u) return;

    const int b = n >> 10;
    const int f = n & (F_C - 1);
    const float* __restrict__ xp = in + (size_t)b * T * F_C + f;
    float* __restrict__ ip = imem + (size_t)b * (T + 1) * F_C + f;
    float* __restrict__ sp = spk  + (size_t)b * (T + 1) * F_C + f;

    const float cs  = sa::f_CUR_SCALE();
    const float oma = sa::f_ONE_MINUS_A();
    const float itm = sa::f_INV_TAU_M();
    const float dt  = sa::f_DT_S();
    const float kah = sa::f_K_AHP();
    const float kre = sa::f_K_REF();
    const float zth = sa::f_Z_TH();
    const float rg  = sa::f_R();
    const float aah = sa::f_I_TH_AHP();
    const float are = sa::f_I_REF_ADD();

    ip[0] = 0.0f;
    float z = 0.0f, ahp = 0.0f, ref = 0.0f;
    float lastf = 0.0f;
    for (int t = 0; t < T; t++) {
        const float x = xp[(size_t)t * F_C];
        const float i_net = fmaf(x, cs, -ahp - ref);
        z = fmaf(dt, fmaf(-oma, z, i_net) * itm, z);
        const bool fd = (z >= zth);
        z = fd ? 0.0f : z;
        ahp = fmaf(ahp, -kah, ahp);
        ref = fmaf(ref, -kre, ref);
        if (fd) { ahp += aah; ref += are; }
        const float ff = fd ? 1.0f : 0.0f;
        ip[(size_t)(t + 1) * F_C] = z * rg;
        sp[(size_t)t * F_C] = ff;
        lastf = ff;
    }
    sp[(size_t)T * F_C] = lastf;
}

// ---------------------------------------------------------------------------
extern "C" void kernel_launch(void* const* d_in, const int* in_sizes, int n_in,
                              void* d_out, int out_size)
{
    (void)n_in;
    const int T = in_sizes[0] / (B_C * F_C);       // 2000
    const int K = (T + L_C - 1) / L_C;             // 80
    const int half = out_size / 2;

    const float* in = (const float*)d_in[0];
    float* imem_out = (float*)d_out;
    float* spk_out  = (float*)d_out + half;

    const double a_d = 1.0 - sa::d_DT_S * 0.2 / sa::d_TAU_M;   // 0.99
    const float  aL  = (float)std::pow(a_d, (double)L_C);

    static bool attr_done = false;
    if (!attr_done) {
        cudaFuncSetAttribute(sa_main,
                             cudaFuncAttributeMaxDynamicSharedMemorySize,
                             SMEM_BYTES);
        attr_done = true;
    }

    sa_init<<<(K * SLICES + 255) / 256, 256>>>(K);
    sa_main<<<K * SLICES, THR, SMEM_BYTES>>>(in, imem_out, spk_out, T, aL);
    sa_fallback<<<N_C / 128, 128>>>(in, imem_out, spk_out, T);
}